// round 1
// baseline (speedup 1.0000x reference)
#include <cuda_runtime.h>

#define SS 48
#define TT 16
#define BB 2
#define NTOT (BB*SS*SS*SS*TT)   // 3,538,944

// accumulators: 0=phy, 1=main1, 2=main2, 3=t1, 4=t2
__device__ double g_acc[5];

__global__ void k_init() {
    int i = threadIdx.x;
    if (i < 5) g_acc[i] = 0.0;
}

__device__ __forceinline__ void loadrow(const float* __restrict__ p, int off, float r[4]) {
    float4 v = __ldg(reinterpret_cast<const float4*>(p + off));
    r[0] = v.x; r[1] = v.y; r[2] = v.z; r[3] = v.w;
}

// first derivative of torch.gradient (unit spacing)
__device__ __forceinline__ void d1(const float m1[4], const float c[4], const float p1[4],
                                   int i, int n, float out[4]) {
#pragma unroll
    for (int j = 0; j < 4; j++) {
        float v;
        if (i == 0)          v = p1[j] - c[j];
        else if (i == n - 1) v = c[j] - m1[j];
        else                 v = 0.5f * (p1[j] - m1[j]);
        out[j] = v;
    }
}

// grad(grad(f)) along one axis: 5 boundary cases, exact composition
__device__ __forceinline__ void d2acc(const float m2[4], const float m1[4], const float c[4],
                                      const float p1[4], const float p2[4],
                                      int i, int n, float out[4]) {
#pragma unroll
    for (int j = 0; j < 4; j++) {
        float h;
        if (i == 0)          h = 0.5f * c[j]  - p1[j]         + 0.5f * p2[j];
        else if (i == 1)     h = 0.5f * m1[j] - 0.75f * c[j]  + 0.25f * p2[j];
        else if (i == n - 1) h = 0.5f * m2[j] - m1[j]         + 0.5f * c[j];
        else if (i == n - 2) h = 0.25f * m2[j] - 0.75f * c[j] + 0.5f * p1[j];
        else                 h = 0.25f * (m2[j] + p2[j]) - 0.5f * c[j];
        out[j] += h;
    }
}

// Process one velocity component: returns a = dW/dt + (V·∇)W - Re*lapW,
// and the own-axis first derivative (for divergence e4).
// AXIS: 0 = y, 1 = x, 2 = z.
template <int AXIS>
__device__ __forceinline__ void proc_comp(
    const float* __restrict__ V, int cbase,
    int sc, int s_ym1, int s_ym2, int s_yp1, int s_yp2,
    int s_xm1, int s_xm2, int s_xp1, int s_xp2,
    int s_zm1, int s_zm2, int s_zp1, int s_zp2,
    int y, int x, int z, int tc,
    const float cW[4], const float cVy[4], const float cVx[4], const float cVz[4],
    float Re, float a[4], float ownd[4])
{
    (void)sc;
    // t-neighbors via shuffle (lane = z*4 + tc within warp; tc minor)
    float wprev = __shfl_up_sync(0xffffffffu, cW[3], 1);
    float wnext = __shfl_down_sync(0xffffffffu, cW[0], 1);

    float rym1[4], rym2[4], ryp1[4], ryp2[4];
    float rxm1[4], rxm2[4], rxp1[4], rxp2[4];
    float rzm1[4], rzm2[4], rzp1[4], rzp2[4];
    loadrow(V, s_ym1 * 48 + cbase, rym1);
    loadrow(V, s_ym2 * 48 + cbase, rym2);
    loadrow(V, s_yp1 * 48 + cbase, ryp1);
    loadrow(V, s_yp2 * 48 + cbase, ryp2);
    loadrow(V, s_xm1 * 48 + cbase, rxm1);
    loadrow(V, s_xm2 * 48 + cbase, rxm2);
    loadrow(V, s_xp1 * 48 + cbase, rxp1);
    loadrow(V, s_xp2 * 48 + cbase, rxp2);
    loadrow(V, s_zm1 * 48 + cbase, rzm1);
    loadrow(V, s_zm2 * 48 + cbase, rzm2);
    loadrow(V, s_zp1 * 48 + cbase, rzp1);
    loadrow(V, s_zp2 * 48 + cbase, rzp2);

    float dy[4], dx[4], dz[4];
    d1(rym1, cW, ryp1, y, SS, dy);
    d1(rxm1, cW, rxp1, x, SS, dx);
    d1(rzm1, cW, rzp1, z, SS, dz);

    float lap[4] = {0.f, 0.f, 0.f, 0.f};
    d2acc(rym2, rym1, cW, ryp1, ryp2, y, SS, lap);
    d2acc(rxm2, rxm1, cW, rxp1, rxp2, x, SS, lap);
    d2acc(rzm2, rzm1, cW, rzp1, rzp2, z, SS, lap);

    float dt[4];
    const int t0 = tc * 4;
    dt[0] = (t0 == 0)       ? (cW[1] - cW[0]) : 0.5f * (cW[1] - wprev);
    dt[1] = 0.5f * (cW[2] - cW[0]);
    dt[2] = 0.5f * (cW[3] - cW[1]);
    dt[3] = (t0 == TT - 4)  ? (cW[3] - cW[2]) : 0.5f * (wnext - cW[2]);

#pragma unroll
    for (int j = 0; j < 4; j++) {
        a[j] = dt[j] + cVx[j] * dx[j] + cVy[j] * dy[j] + cVz[j] * dz[j] - Re * lap[j];
        ownd[j] = (AXIS == 0) ? dy[j] : (AXIS == 1) ? dx[j] : dz[j];
    }
}

__global__ void __launch_bounds__(192) k_phy(
    const float* __restrict__ V, const float* __restrict__ P,
    const float* __restrict__ F, const float* __restrict__ RePtr)
{
    const int tid = threadIdx.x;
    const int tc  = tid & 3;      // t-chunk 0..3 (4 t-values each)
    const int z   = tid >> 2;     // 0..47
    const int bi  = blockIdx.x;   // (b,y,x)
    const int x   = bi % SS;
    const int y   = (bi / SS) % SS;
    const int b   = bi / (SS * SS);
    const int toff = tc * 4;
    const float Re = __ldg(RePtr);

    const int ym1 = max(y - 1, 0), ym2 = max(y - 2, 0);
    const int yp1 = min(y + 1, SS - 1), yp2 = min(y + 2, SS - 1);
    const int xm1 = max(x - 1, 0), xm2 = max(x - 2, 0);
    const int xp1 = min(x + 1, SS - 1), xp2 = min(x + 2, SS - 1);
    const int zm1 = max(z - 1, 0), zm2 = max(z - 2, 0);
    const int zp1 = min(z + 1, SS - 1), zp2 = min(z + 2, SS - 1);

    const int sbyx  = ((b * SS + y) * SS + x) * SS;
    const int sc    = sbyx + z;
    const int s_ym1 = ((b * SS + ym1) * SS + x) * SS + z;
    const int s_ym2 = ((b * SS + ym2) * SS + x) * SS + z;
    const int s_yp1 = ((b * SS + yp1) * SS + x) * SS + z;
    const int s_yp2 = ((b * SS + yp2) * SS + x) * SS + z;
    const int s_xm1 = ((b * SS + y) * SS + xm1) * SS + z;
    const int s_xm2 = ((b * SS + y) * SS + xm2) * SS + z;
    const int s_xp1 = ((b * SS + y) * SS + xp1) * SS + z;
    const int s_xp2 = ((b * SS + y) * SS + xp2) * SS + z;
    const int s_zm1 = sbyx + zm1;
    const int s_zm2 = sbyx + zm2;
    const int s_zp1 = sbyx + zp1;
    const int s_zp2 = sbyx + zp2;

    // center rows of Vy, Vx, Vz (components 0,1,2)
    float cVy[4], cVx[4], cVz[4];
    loadrow(V, sc * 48 + 0  + toff, cVy);
    loadrow(V, sc * 48 + 16 + toff, cVx);
    loadrow(V, sc * 48 + 32 + toff, cVz);

    float aY[4], aX[4], aZ[4], dYy[4], dXx[4], dZz[4];
    proc_comp<0>(V, 0  + toff, sc, s_ym1, s_ym2, s_yp1, s_yp2,
                 s_xm1, s_xm2, s_xp1, s_xp2, s_zm1, s_zm2, s_zp1, s_zp2,
                 y, x, z, tc, cVy, cVy, cVx, cVz, Re, aY, dYy);
    proc_comp<1>(V, 16 + toff, sc, s_ym1, s_ym2, s_yp1, s_yp2,
                 s_xm1, s_xm2, s_xp1, s_xp2, s_zm1, s_zm2, s_zp1, s_zp2,
                 y, x, z, tc, cVx, cVy, cVx, cVz, Re, aX, dXx);
    proc_comp<2>(V, 32 + toff, sc, s_ym1, s_ym2, s_yp1, s_yp2,
                 s_xm1, s_xm2, s_xp1, s_xp2, s_zm1, s_zm2, s_zp1, s_zp2,
                 y, x, z, tc, cVz, cVy, cVx, cVz, Re, aZ, dZz);

    // pressure gradient
    float pc[4], pym1[4], pyp1[4], pxm1[4], pxp1[4], pzm1[4], pzp1[4];
    loadrow(P, sc    * 16 + toff, pc);
    loadrow(P, s_ym1 * 16 + toff, pym1);
    loadrow(P, s_yp1 * 16 + toff, pyp1);
    loadrow(P, s_xm1 * 16 + toff, pxm1);
    loadrow(P, s_xp1 * 16 + toff, pxp1);
    loadrow(P, s_zm1 * 16 + toff, pzm1);
    loadrow(P, s_zp1 * 16 + toff, pzp1);
    float dPdy[4], dPdx[4], dPdz[4];
    d1(pym1, pc, pyp1, y, SS, dPdy);
    d1(pxm1, pc, pxp1, x, SS, dPdx);
    d1(pzm1, pc, pzp1, z, SS, dPdz);

    // forcing
    float fy[4], fx[4], fz[4];
    loadrow(F, sc * 48 + 0  + toff, fy);
    loadrow(F, sc * 48 + 16 + toff, fx);
    loadrow(F, sc * 48 + 32 + toff, fz);

    float local = 0.f;
#pragma unroll
    for (int j = 0; j < 4; j++) {
        float e1 = aY[j] + dPdy[j] + fy[j];
        float e2 = aX[j] + dPdx[j] + fx[j];
        float e3 = aZ[j] + dPdz[j] + fz[j];
        float e4 = dXx[j] + dYy[j] + dZz[j];
        local += e1 * e1 + e2 * e2 + e3 * e3 + e4 * e4;
    }

    // block reduce (6 warps)
#pragma unroll
    for (int off = 16; off; off >>= 1)
        local += __shfl_down_sync(0xffffffffu, local, off);
    __shared__ float ws[6];
    if ((tid & 31) == 0) ws[tid >> 5] = local;
    __syncthreads();
    if (tid == 0) {
        float s = ws[0] + ws[1] + ws[2] + ws[3] + ws[4] + ws[5];
        atomicAdd(&g_acc[0], (double)s);
    }
}

__global__ void __launch_bounds__(256) k_main(
    const float* __restrict__ C, const float* __restrict__ X,
    const float* __restrict__ X1, const float* __restrict__ Y,
    const float* __restrict__ XL)
{
    const int g = blockIdx.x * 256 + threadIdx.x;   // chunk id
    const int base = g * 4;
    float4 c4  = __ldg(reinterpret_cast<const float4*>(C + base));
    float4 x4  = __ldg(reinterpret_cast<const float4*>(X + base));
    float4 x14 = __ldg(reinterpret_cast<const float4*>(X1 + base));
    float4 y4  = __ldg(reinterpret_cast<const float4*>(Y + base));
    const int tc = g & 3;
    float prev = (tc == 0) ? __ldg(XL + (g >> 2)) : __ldg(Y + base - 1);

    float ya[4]  = {y4.x,  y4.y,  y4.z,  y4.w};
    float ca[4]  = {c4.x,  c4.y,  c4.z,  c4.w};
    float xa[4]  = {x4.x,  x4.y,  x4.z,  x4.w};
    float x1a[4] = {x14.x, x14.y, x14.z, x14.w};
    float yl[4]  = {prev, ya[0], ya[1], ya[2]};

    float m1 = 0.f, m2 = 0.f, t1 = 0.f, t2 = 0.f;
#pragma unroll
    for (int j = 0; j < 4; j++) {
        float a = x1a[j] - ya[j]; m1 += a * a;
        float bdf = xa[j] - ya[j]; m2 += bdf * bdf;
        float cdf = ca[j] - ya[j]; t2 += cdf * cdf;
        float ddf = yl[j] - ya[j]; t1 += ddf * ddf;
    }

#pragma unroll
    for (int off = 16; off; off >>= 1) {
        m1 += __shfl_down_sync(0xffffffffu, m1, off);
        m2 += __shfl_down_sync(0xffffffffu, m2, off);
        t1 += __shfl_down_sync(0xffffffffu, t1, off);
        t2 += __shfl_down_sync(0xffffffffu, t2, off);
    }
    __shared__ float sm[8][4];
    const int w = threadIdx.x >> 5, l = threadIdx.x & 31;
    if (l == 0) { sm[w][0] = m1; sm[w][1] = m2; sm[w][2] = t1; sm[w][3] = t2; }
    __syncthreads();
    if (threadIdx.x == 0) {
        float a = 0.f, bq = 0.f, cq = 0.f, dq = 0.f;
#pragma unroll
        for (int i = 0; i < 8; i++) { a += sm[i][0]; bq += sm[i][1]; cq += sm[i][2]; dq += sm[i][3]; }
        atomicAdd(&g_acc[1], (double)a);
        atomicAdd(&g_acc[2], (double)bq);
        atomicAdd(&g_acc[3], (double)cq);
        atomicAdd(&g_acc[4], (double)dq);
    }
}

__global__ void k_fin(float* __restrict__ out) {
    const double invN = 1.0 / (double)NTOT;
    double phy = g_acc[0] * invN;
    double m1  = g_acc[1] * invN;
    double m2  = g_acc[2] * invN;
    double t1  = g_acc[3] * invN;
    double t2  = g_acc[4] * invN;
    out[0] = (float)m1;
    out[1] = (float)m2;
    out[2] = (float)phy;
    out[3] = (float)((t1 < t2) ? (t2 - t1) : 0.0);
}

extern "C" void kernel_launch(void* const* d_in, const int* in_sizes, int n_in,
                              void* d_out, int out_size) {
    (void)in_sizes; (void)n_in; (void)out_size;
    const float* C  = (const float*)d_in[0];
    const float* V  = (const float*)d_in[1];
    const float* P  = (const float*)d_in[2];
    const float* X  = (const float*)d_in[3];
    const float* X1 = (const float*)d_in[4];
    const float* F  = (const float*)d_in[5];
    const float* Re = (const float*)d_in[6];
    const float* XL = (const float*)d_in[7];
    const float* Y  = (const float*)d_in[8];
    float* out = (float*)d_out;

    k_init<<<1, 32>>>();
    k_phy<<<BB * SS * SS, 192>>>(V, P, F, Re);
    k_main<<<NTOT / 4 / 256, 256>>>(C, X, X1, Y, XL);
    k_fin<<<1, 1>>>(out);
}

// round 2
// speedup vs baseline: 1.1306x; 1.1306x over previous
#include <cuda_runtime.h>

#define SS 48
#define TT 16
#define BB 2
#define NTOT (BB*SS*SS*SS*TT)   // 3,538,944

#define XT 4                    // x-tile per block
#define NXC (XT+4)              // 8 V columns in smem (halo 2)
#define NPC (XT+2)              // 6 P columns in smem (halo 1)
#define VROW 52                 // padded row (floats) for V: 48 data + 4 pad
#define PROW 20                 // padded row (floats) for P: 16 data + 4 pad
#define SMEM_FLOATS (NXC*48*VROW + NPC*48*PROW)
#define SMEM_BYTES  (SMEM_FLOATS*4)     // 102912

#define PHY_BLOCKS (BB*SS*(SS/XT))      // 1152
#define MAIN_BLOCKS 1152                // NTOT/4/768
#define FUSED_BLOCKS (PHY_BLOCKS + MAIN_BLOCKS)

__device__ double g_phy_part[PHY_BLOCKS];
__device__ double g_mp[MAIN_BLOCKS * 4];

__device__ __forceinline__ void ld4g(const float* __restrict__ p, int off, float r[4]) {
    float4 v = __ldg(reinterpret_cast<const float4*>(p + off));
    r[0] = v.x; r[1] = v.y; r[2] = v.z; r[3] = v.w;
}
__device__ __forceinline__ void ld4s(const float* p, float r[4]) {
    float4 v = *reinterpret_cast<const float4*>(p);
    r[0] = v.x; r[1] = v.y; r[2] = v.z; r[3] = v.w;
}

// first derivative of torch.gradient (unit spacing)
__device__ __forceinline__ void d1(const float m1[4], const float c[4], const float p1[4],
                                   int i, int n, float out[4]) {
#pragma unroll
    for (int j = 0; j < 4; j++) {
        float v;
        if (i == 0)          v = p1[j] - c[j];
        else if (i == n - 1) v = c[j] - m1[j];
        else                 v = 0.5f * (p1[j] - m1[j]);
        out[j] = v;
    }
}

// grad(grad(f)) along one axis: 5 boundary cases, exact composition
__device__ __forceinline__ void d2acc(const float m2[4], const float m1[4], const float c[4],
                                      const float p1[4], const float p2[4],
                                      int i, int n, float out[4]) {
#pragma unroll
    for (int j = 0; j < 4; j++) {
        float h;
        if (i == 0)          h = 0.5f * c[j]  - p1[j]         + 0.5f * p2[j];
        else if (i == 1)     h = 0.5f * m1[j] - 0.75f * c[j]  + 0.25f * p2[j];
        else if (i == n - 1) h = 0.5f * m2[j] - m1[j]         + 0.5f * c[j];
        else if (i == n - 2) h = 0.25f * m2[j] - 0.75f * c[j] + 0.5f * p1[j];
        else                 h = 0.25f * (m2[j] + p2[j]) - 0.5f * c[j];
        out[j] += h;
    }
}

__global__ void __launch_bounds__(768, 1) k_fused(
    const float* __restrict__ V, const float* __restrict__ P,
    const float* __restrict__ F, const float* __restrict__ RePtr,
    const float* __restrict__ C, const float* __restrict__ X,
    const float* __restrict__ X1, const float* __restrict__ Y,
    const float* __restrict__ XL)
{
    const int tid = threadIdx.x;

    if (blockIdx.x >= PHY_BLOCKS) {
        // ---------------- streaming MSE branch ----------------
        const int blk = blockIdx.x - PHY_BLOCKS;
        const int g = blk * 768 + tid;   // chunk id (4 t-values)
        const int base = g * 4;
        float ca[4], xa[4], x1a[4], ya[4];
        ld4g(C, base, ca); ld4g(X, base, xa); ld4g(X1, base, x1a); ld4g(Y, base, ya);
        const int tc = g & 3;
        float prev = (tc == 0) ? __ldg(XL + (g >> 2)) : __ldg(Y + base - 1);
        float yl[4] = {prev, ya[0], ya[1], ya[2]};

        float m1 = 0.f, m2 = 0.f, t1 = 0.f, t2 = 0.f;
#pragma unroll
        for (int j = 0; j < 4; j++) {
            float a = x1a[j] - ya[j]; m1 += a * a;
            float bv = xa[j]  - ya[j]; m2 += bv * bv;
            float cv = ca[j]  - ya[j]; t2 += cv * cv;
            float dv = yl[j]  - ya[j]; t1 += dv * dv;
        }
#pragma unroll
        for (int off = 16; off; off >>= 1) {
            m1 += __shfl_down_sync(0xffffffffu, m1, off);
            m2 += __shfl_down_sync(0xffffffffu, m2, off);
            t1 += __shfl_down_sync(0xffffffffu, t1, off);
            t2 += __shfl_down_sync(0xffffffffu, t2, off);
        }
        __shared__ float sm2[24][4];
        const int w = tid >> 5, l = tid & 31;
        if (l == 0) { sm2[w][0] = m1; sm2[w][1] = m2; sm2[w][2] = t1; sm2[w][3] = t2; }
        __syncthreads();
        if (tid == 0) {
            float a = 0.f, b2 = 0.f, c2 = 0.f, d2 = 0.f;
#pragma unroll
            for (int i = 0; i < 24; i++) { a += sm2[i][0]; b2 += sm2[i][1]; c2 += sm2[i][2]; d2 += sm2[i][3]; }
            g_mp[blk * 4 + 0] = (double)a;
            g_mp[blk * 4 + 1] = (double)b2;
            g_mp[blk * 4 + 2] = (double)c2;
            g_mp[blk * 4 + 3] = (double)d2;
        }
        return;
    }

    // ---------------- physics (stencil) branch ----------------
    extern __shared__ float smf[];
    float* sV = smf;                       // [NXC][48][VROW]
    float* sP = smf + NXC * 48 * VROW;     // [NPC][48][PROW]

    const int bi = blockIdx.x;
    const int xt = bi % (SS / XT);
    const int y  = (bi / (SS / XT)) % SS;
    const int b  = bi / ((SS / XT) * SS);
    const int x0 = xt * XT;

    // ---- cooperative fill ----
    {
        const int colbase = ((b * SS + y) * SS);  // spatial (b,y,*) base
        // V: 8 columns x 576 float4 each (column = 48z * 48 floats contiguous)
#pragma unroll
        for (int it = 0; it < 6; it++) {
            int idx = it * 768 + tid;          // 0..4607
            int col = idx / 576;
            int r   = idx - col * 576;
            int gx  = min(max(x0 - 2 + col, 0), SS - 1);
            float4 v = __ldg(reinterpret_cast<const float4*>(V + (colbase + gx) * 2304 + r * 4));
            int zz = r / 12, off = (r - zz * 12) * 4;
            *reinterpret_cast<float4*>(&sV[(col * 48 + zz) * VROW + off]) = v;
        }
        // P: 6 columns x 192 float4 each
        int idx = tid;
#pragma unroll
        for (int it = 0; it < 2; it++, idx += 768) {
            if (idx < NPC * 192) {
                int col = idx / 192;
                int r   = idx - col * 192;
                int gx  = min(max(x0 - 1 + col, 0), SS - 1);
                float4 v = __ldg(reinterpret_cast<const float4*>(P + (colbase + gx) * 768 + r * 4));
                int zz = r / 4, off = (r - zz * 4) * 4;
                *reinterpret_cast<float4*>(&sP[(col * 48 + zz) * PROW + off]) = v;
            }
        }
    }
    __syncthreads();

    const int tc = tid & 3;
    const int z  = (tid >> 2) % 48;
    const int xk = (tid >> 2) / 48;
    const int x  = x0 + xk;
    const int xi = xk + 2;    // center V column in tile
    const int pxi = xk + 1;   // center P column in tile
    const int toff = tc * 4;
    const float Re = __ldg(RePtr);

    const int ym1 = max(y - 1, 0), ym2 = max(y - 2, 0);
    const int yp1 = min(y + 1, SS - 1), yp2 = min(y + 2, SS - 1);
    const int zm1 = max(z - 1, 0), zm2 = max(z - 2, 0);
    const int zp1 = min(z + 1, SS - 1), zp2 = min(z + 2, SS - 1);

    const int sc    = ((b * SS + y)   * SS + x) * SS + z;
    const int s_ym1 = ((b * SS + ym1) * SS + x) * SS + z;
    const int s_ym2 = ((b * SS + ym2) * SS + x) * SS + z;
    const int s_yp1 = ((b * SS + yp1) * SS + x) * SS + z;
    const int s_yp2 = ((b * SS + yp2) * SS + x) * SS + z;

    // center velocities (all 3 components)
    float cVv[3][4];
#pragma unroll
    for (int c = 0; c < 3; c++)
        ld4s(&sV[(xi * 48 + z) * VROW + c * 16 + toff], cVv[c]);

    // pressure gradient: z/x from smem, y from gmem
    float dP[3][4];
    {
        float pc[4], pzm[4], pzp[4], pxm[4], pxp[4], pym[4], pyp[4];
        ld4s(&sP[(pxi * 48 + z)   * PROW + toff], pc);
        ld4s(&sP[(pxi * 48 + zm1) * PROW + toff], pzm);
        ld4s(&sP[(pxi * 48 + zp1) * PROW + toff], pzp);
        ld4s(&sP[((pxi - 1) * 48 + z) * PROW + toff], pxm);
        ld4s(&sP[((pxi + 1) * 48 + z) * PROW + toff], pxp);
        ld4g(P, s_ym1 * 16 + toff, pym);
        ld4g(P, s_yp1 * 16 + toff, pyp);
        d1(pym, pc, pyp, y, SS, dP[0]);   // dPdy
        d1(pxm, pc, pxp, x, SS, dP[1]);   // dPdx
        d1(pzm, pc, pzp, z, SS, dP[2]);   // dPdz
    }

    float e4[4] = {0.f, 0.f, 0.f, 0.f};
    float local = 0.f;

#pragma unroll
    for (int c = 0; c < 3; c++) {
        const int co = c * 16 + toff;
        float cw[4];
#pragma unroll
        for (int j = 0; j < 4; j++) cw[j] = cVv[c][j];

        float wprev = __shfl_up_sync(0xffffffffu, cw[3], 1);
        float wnext = __shfl_down_sync(0xffffffffu, cw[0], 1);

        float rzm1[4], rzm2[4], rzp1[4], rzp2[4];
        ld4s(&sV[(xi * 48 + zm1) * VROW + co], rzm1);
        ld4s(&sV[(xi * 48 + zm2) * VROW + co], rzm2);
        ld4s(&sV[(xi * 48 + zp1) * VROW + co], rzp1);
        ld4s(&sV[(xi * 48 + zp2) * VROW + co], rzp2);

        float rxm1[4], rxm2[4], rxp1[4], rxp2[4];
        ld4s(&sV[((xi - 1) * 48 + z) * VROW + co], rxm1);
        ld4s(&sV[((xi - 2) * 48 + z) * VROW + co], rxm2);
        ld4s(&sV[((xi + 1) * 48 + z) * VROW + co], rxp1);
        ld4s(&sV[((xi + 2) * 48 + z) * VROW + co], rxp2);

        float rym1[4], rym2[4], ryp1[4], ryp2[4];
        ld4g(V, s_ym1 * 48 + co, rym1);
        ld4g(V, s_ym2 * 48 + co, rym2);
        ld4g(V, s_yp1 * 48 + co, ryp1);
        ld4g(V, s_yp2 * 48 + co, ryp2);

        float dyv[4], dxv[4], dzv[4];
        d1(rym1, cw, ryp1, y, SS, dyv);
        d1(rxm1, cw, rxp1, x, SS, dxv);
        d1(rzm1, cw, rzp1, z, SS, dzv);

        float lap[4] = {0.f, 0.f, 0.f, 0.f};
        d2acc(rym2, rym1, cw, ryp1, ryp2, y, SS, lap);
        d2acc(rxm2, rxm1, cw, rxp1, rxp2, x, SS, lap);
        d2acc(rzm2, rzm1, cw, rzp1, rzp2, z, SS, lap);

        float dt[4];
        dt[0] = (tc == 0) ? (cw[1] - cw[0]) : 0.5f * (cw[1] - wprev);
        dt[1] = 0.5f * (cw[2] - cw[0]);
        dt[2] = 0.5f * (cw[3] - cw[1]);
        dt[3] = (tc == 3) ? (cw[3] - cw[2]) : 0.5f * (wnext - cw[2]);

        float fr[4];
        ld4g(F, sc * 48 + co, fr);

#pragma unroll
        for (int j = 0; j < 4; j++) {
            float e = dt[j] + cVv[1][j] * dxv[j] + cVv[0][j] * dyv[j] + cVv[2][j] * dzv[j]
                    - Re * lap[j] + dP[c][j] + fr[j];
            local += e * e;
            float ow = (c == 0) ? dyv[j] : (c == 1) ? dxv[j] : dzv[j];
            e4[j] += ow;
        }
    }
#pragma unroll
    for (int j = 0; j < 4; j++) local += e4[j] * e4[j];

    // block reduce (24 warps)
#pragma unroll
    for (int off = 16; off; off >>= 1)
        local += __shfl_down_sync(0xffffffffu, local, off);
    __shared__ float ws[24];
    if ((tid & 31) == 0) ws[tid >> 5] = local;
    __syncthreads();
    if (tid == 0) {
        float s = 0.f;
#pragma unroll
        for (int i = 0; i < 24; i++) s += ws[i];
        g_phy_part[bi] = (double)s;
    }
}

__global__ void k_fin(float* __restrict__ out) {
    const int tid = threadIdx.x;
    double s0 = 0.0, s1 = 0.0, s2 = 0.0, s3 = 0.0, s4 = 0.0;
    for (int i = tid; i < PHY_BLOCKS; i += 256) s0 += g_phy_part[i];
    for (int i = tid; i < MAIN_BLOCKS; i += 256) {
        s1 += g_mp[i * 4 + 0];
        s2 += g_mp[i * 4 + 1];
        s3 += g_mp[i * 4 + 2];
        s4 += g_mp[i * 4 + 3];
    }
#pragma unroll
    for (int off = 16; off; off >>= 1) {
        s0 += __shfl_down_sync(0xffffffffu, s0, off);
        s1 += __shfl_down_sync(0xffffffffu, s1, off);
        s2 += __shfl_down_sync(0xffffffffu, s2, off);
        s3 += __shfl_down_sync(0xffffffffu, s3, off);
        s4 += __shfl_down_sync(0xffffffffu, s4, off);
    }
    __shared__ double sh[8][5];
    const int w = tid >> 5, l = tid & 31;
    if (l == 0) { sh[w][0] = s0; sh[w][1] = s1; sh[w][2] = s2; sh[w][3] = s3; sh[w][4] = s4; }
    __syncthreads();
    if (tid == 0) {
        double a0 = 0, a1 = 0, a2 = 0, a3 = 0, a4 = 0;
#pragma unroll
        for (int i = 0; i < 8; i++) { a0 += sh[i][0]; a1 += sh[i][1]; a2 += sh[i][2]; a3 += sh[i][3]; a4 += sh[i][4]; }
        const double invN = 1.0 / (double)NTOT;
        double phy = a0 * invN;
        double m1  = a1 * invN;
        double m2  = a2 * invN;
        double t1  = a3 * invN;
        double t2  = a4 * invN;
        out[0] = (float)m1;
        out[1] = (float)m2;
        out[2] = (float)phy;
        out[3] = (float)((t1 < t2) ? (t2 - t1) : 0.0);
    }
}

extern "C" void kernel_launch(void* const* d_in, const int* in_sizes, int n_in,
                              void* d_out, int out_size) {
    (void)in_sizes; (void)n_in; (void)out_size;
    const float* C  = (const float*)d_in[0];
    const float* V  = (const float*)d_in[1];
    const float* P  = (const float*)d_in[2];
    const float* X  = (const float*)d_in[3];
    const float* X1 = (const float*)d_in[4];
    const float* F  = (const float*)d_in[5];
    const float* Re = (const float*)d_in[6];
    const float* XL = (const float*)d_in[7];
    const float* Y  = (const float*)d_in[8];
    float* out = (float*)d_out;

    cudaFuncSetAttribute(k_fused, cudaFuncAttributeMaxDynamicSharedMemorySize, SMEM_BYTES);
    k_fused<<<FUSED_BLOCKS, 768, SMEM_BYTES>>>(V, P, F, Re, C, X, X1, Y, XL);
    k_fin<<<1, 256>>>(out);
}

// round 3
// speedup vs baseline: 1.1553x; 1.0219x over previous
#include <cuda_runtime.h>

#define SS 48
#define TT 16
#define BB 2
#define NTOT (BB*SS*SS*SS*TT)   // 3,538,944

#define XT 4                    // x-tile per block
#define NXC (XT+4)              // 8 V columns in smem (halo 2)
#define PHY_BLOCKS (BB*SS*(SS/XT))      // 1152
#define MAIN_BLOCKS 1152                // NTOT/4/768
#define FUSED_BLOCKS (PHY_BLOCKS + MAIN_BLOCKS)
#define SMEM_BYTES (NXC*48*48*4)        // 73728

__device__ double g_phy_part[PHY_BLOCKS];
__device__ double g_mp[MAIN_BLOCKS * 4];
__device__ unsigned int g_counter = 0;

__device__ __forceinline__ void ld4g(const float* __restrict__ p, int off, float r[4]) {
    float4 v = __ldg(reinterpret_cast<const float4*>(p + off));
    r[0] = v.x; r[1] = v.y; r[2] = v.z; r[3] = v.w;
}
__device__ __forceinline__ void ld4s(const float* p, float r[4]) {
    float4 v = *reinterpret_cast<const float4*>(p);
    r[0] = v.x; r[1] = v.y; r[2] = v.z; r[3] = v.w;
}

// 3-tap coefficients for torch.gradient first derivative (with clamped reads)
__device__ __forceinline__ void coef1(int i, float a[3]) {
    bool lo = (i == 0), hi = (i == SS - 1);
    a[0] = lo ? 0.f  : (hi ? -1.f : -0.5f);
    a[1] = lo ? -1.f : (hi ?  1.f :  0.f );
    a[2] = lo ? 1.f  : (hi ?  0.f :  0.5f);
}
// 5-tap coefficients for grad(grad(f)) (exact composition, with clamped reads)
__device__ __forceinline__ void coef2(int i, float a[5]) {
    // default interior
    float c0 = 0.25f, c1 = 0.f, c2 = -0.5f, c3 = 0.f, c4 = 0.25f;
    if (i == 0)      { c0 = 0.f;   c1 = 0.f;   c2 = 0.5f;   c3 = -1.f;  c4 = 0.5f; }
    if (i == 1)      { c0 = 0.f;   c1 = 0.5f;  c2 = -0.75f; c3 = 0.f;   c4 = 0.25f; }
    if (i == SS - 2) { c0 = 0.25f; c1 = 0.f;   c2 = -0.75f; c3 = 0.5f;  c4 = 0.f; }
    if (i == SS - 1) { c0 = 0.5f;  c1 = -1.f;  c2 = 0.5f;   c3 = 0.f;   c4 = 0.f; }
    a[0] = c0; a[1] = c1; a[2] = c2; a[3] = c3; a[4] = c4;
}

__global__ void k_nop() {}

__global__ void __launch_bounds__(768, 1) k_fused(
    const float* __restrict__ V, const float* __restrict__ P,
    const float* __restrict__ F, const float* __restrict__ RePtr,
    const float* __restrict__ C, const float* __restrict__ X,
    const float* __restrict__ X1, const float* __restrict__ Y,
    const float* __restrict__ XL, float* __restrict__ out)
{
    const int tid = threadIdx.x;

    if (blockIdx.x >= PHY_BLOCKS) {
        // ---------------- streaming MSE branch ----------------
        const int blk = blockIdx.x - PHY_BLOCKS;
        const int g = blk * 768 + tid;   // chunk id (4 t-values)
        const int base = g * 4;
        float ca[4], xa[4], x1a[4], ya[4];
        ld4g(C, base, ca); ld4g(X, base, xa); ld4g(X1, base, x1a); ld4g(Y, base, ya);
        const int tcc = g & 3;
        float prev = (tcc == 0) ? __ldg(XL + (g >> 2)) : __ldg(Y + base - 1);
        float yl[4] = {prev, ya[0], ya[1], ya[2]};

        float m1 = 0.f, m2 = 0.f, t1 = 0.f, t2 = 0.f;
#pragma unroll
        for (int j = 0; j < 4; j++) {
            float a = x1a[j] - ya[j]; m1 += a * a;
            float bv = xa[j]  - ya[j]; m2 += bv * bv;
            float cv = ca[j]  - ya[j]; t2 += cv * cv;
            float dv = yl[j]  - ya[j]; t1 += dv * dv;
        }
#pragma unroll
        for (int off = 16; off; off >>= 1) {
            m1 += __shfl_down_sync(0xffffffffu, m1, off);
            m2 += __shfl_down_sync(0xffffffffu, m2, off);
            t1 += __shfl_down_sync(0xffffffffu, t1, off);
            t2 += __shfl_down_sync(0xffffffffu, t2, off);
        }
        __shared__ float sm2[24][4];
        const int w = tid >> 5, l = tid & 31;
        if (l == 0) { sm2[w][0] = m1; sm2[w][1] = m2; sm2[w][2] = t1; sm2[w][3] = t2; }
        __syncthreads();
        if (tid == 0) {
            float a = 0.f, b2 = 0.f, c2 = 0.f, d2 = 0.f;
#pragma unroll
            for (int i = 0; i < 24; i++) { a += sm2[i][0]; b2 += sm2[i][1]; c2 += sm2[i][2]; d2 += sm2[i][3]; }
            g_mp[blk * 4 + 0] = (double)a;
            g_mp[blk * 4 + 1] = (double)b2;
            g_mp[blk * 4 + 2] = (double)c2;
            g_mp[blk * 4 + 3] = (double)d2;
        }
    } else {
        // ---------------- physics (stencil) branch ----------------
        extern __shared__ float sV[];   // [NXC][48z][48 floats] contiguous columns

        const int bi = blockIdx.x;
        const int xt = bi % (SS / XT);
        const int y  = (bi / (SS / XT)) % SS;
        const int b  = bi / ((SS / XT) * SS);
        const int x0 = xt * XT;
        const int colbase = (b * SS + y) * SS;

        // cooperative fill: 8 columns x 2304 floats, straight copy
#pragma unroll
        for (int it = 0; it < 6; it++) {
            int idx = it * 768 + tid;              // 0..4607 (float4 index)
            int col = idx / 576;
            int r   = idx - col * 576;
            int gx  = min(max(x0 - 2 + col, 0), SS - 1);
            float4 v = __ldg(reinterpret_cast<const float4*>(V + (colbase + gx) * 2304) + r);
            *(reinterpret_cast<float4*>(sV) + col * 576 + r) = v;
        }
        __syncthreads();

        const int tc = tid & 3;
        const int z  = (tid >> 2) % 48;
        const int xk = (tid >> 2) / 48;
        const int x  = x0 + xk;
        const int xi = xk + 2;
        const int toff = tc * 4;
        const float Re = __ldg(RePtr);

        // stencil coefficients (branch-free use afterwards)
        float zc1[3], zc2[5], yc1[3], yc2[5], xc1[3], xc2[5];
        coef1(z, zc1); coef2(z, zc2);
        coef1(y, yc1); coef2(y, yc2);
        coef1(x, xc1); coef2(x, xc2);

        const int ym1 = max(y - 1, 0), ym2 = max(y - 2, 0);
        const int yp1 = min(y + 1, SS - 1), yp2 = min(y + 2, SS - 1);
        const int zm1 = max(z - 1, 0), zm2 = max(z - 2, 0);
        const int zp1 = min(z + 1, SS - 1), zp2 = min(z + 2, SS - 1);

        const int sc    = (colbase + x) * SS + z;
        const int s_ym1 = ((b * SS + ym1) * SS + x) * SS + z;
        const int s_ym2 = ((b * SS + ym2) * SS + x) * SS + z;
        const int s_yp1 = ((b * SS + yp1) * SS + x) * SS + z;
        const int s_yp2 = ((b * SS + yp2) * SS + x) * SS + z;

        // center velocities
        float cVv[3][4];
#pragma unroll
        for (int c = 0; c < 3; c++)
            ld4s(&sV[xi * 2304 + z * 48 + c * 16 + toff], cVv[c]);

        // pressure gradient (all gmem; z/x neighbors are L1 line-mates)
        float dP[3][4];
        {
            float pc[4], pzm[4], pzp[4], pxm[4], pxp[4], pym[4], pyp[4];
            ld4g(P, sc * 16 + toff, pc);
            ld4g(P, ((colbase + x) * SS + zm1) * 16 + toff, pzm);
            ld4g(P, ((colbase + x) * SS + zp1) * 16 + toff, pzp);
            ld4g(P, ((colbase + max(x - 1, 0)) * SS + z) * 16 + toff, pxm);
            ld4g(P, ((colbase + min(x + 1, SS - 1)) * SS + z) * 16 + toff, pxp);
            ld4g(P, s_ym1 * 16 + toff, pym);
            ld4g(P, s_yp1 * 16 + toff, pyp);
#pragma unroll
            for (int j = 0; j < 4; j++) {
                dP[0][j] = yc1[0] * pym[j] + yc1[1] * pc[j] + yc1[2] * pyp[j];
                dP[1][j] = xc1[0] * pxm[j] + xc1[1] * pc[j] + xc1[2] * pxp[j];
                dP[2][j] = zc1[0] * pzm[j] + zc1[1] * pc[j] + zc1[2] * pzp[j];
            }
        }

        float e4[4] = {0.f, 0.f, 0.f, 0.f};
        float local = 0.f;

#pragma unroll
        for (int c = 0; c < 3; c++) {
            const int co = c * 16 + toff;
            float cw[4];
#pragma unroll
            for (int j = 0; j < 4; j++) cw[j] = cVv[c][j];

            float wprev = __shfl_up_sync(0xffffffffu, cw[3], 1);
            float wnext = __shfl_down_sync(0xffffffffu, cw[0], 1);

            float rzm1[4], rzm2[4], rzp1[4], rzp2[4];
            ld4s(&sV[xi * 2304 + zm1 * 48 + co], rzm1);
            ld4s(&sV[xi * 2304 + zm2 * 48 + co], rzm2);
            ld4s(&sV[xi * 2304 + zp1 * 48 + co], rzp1);
            ld4s(&sV[xi * 2304 + zp2 * 48 + co], rzp2);

            float rxm1[4], rxm2[4], rxp1[4], rxp2[4];
            ld4s(&sV[(xi - 1) * 2304 + z * 48 + co], rxm1);
            ld4s(&sV[(xi - 2) * 2304 + z * 48 + co], rxm2);
            ld4s(&sV[(xi + 1) * 2304 + z * 48 + co], rxp1);
            ld4s(&sV[(xi + 2) * 2304 + z * 48 + co], rxp2);

            float rym1[4], rym2[4], ryp1[4], ryp2[4];
            ld4g(V, s_ym1 * 48 + co, rym1);
            ld4g(V, s_ym2 * 48 + co, rym2);
            ld4g(V, s_yp1 * 48 + co, ryp1);
            ld4g(V, s_yp2 * 48 + co, ryp2);

            float fr[4];
            ld4g(F, sc * 48 + co, fr);

#pragma unroll
            for (int j = 0; j < 4; j++) {
                float dyv = yc1[0] * rym1[j] + yc1[1] * cw[j] + yc1[2] * ryp1[j];
                float dxv = xc1[0] * rxm1[j] + xc1[1] * cw[j] + xc1[2] * rxp1[j];
                float dzv = zc1[0] * rzm1[j] + zc1[1] * cw[j] + zc1[2] * rzp1[j];

                float lap = yc2[0] * rym2[j] + yc2[1] * rym1[j] + yc2[2] * cw[j]
                          + yc2[3] * ryp1[j] + yc2[4] * ryp2[j];
                lap      += xc2[0] * rxm2[j] + xc2[1] * rxm1[j] + xc2[2] * cw[j]
                          + xc2[3] * rxp1[j] + xc2[4] * rxp2[j];
                lap      += zc2[0] * rzm2[j] + zc2[1] * rzm1[j] + zc2[2] * cw[j]
                          + zc2[3] * rzp1[j] + zc2[4] * rzp2[j];

                float dt;
                if (j == 0)      dt = (tc == 0) ? (cw[1] - cw[0]) : 0.5f * (cw[1] - wprev);
                else if (j == 1) dt = 0.5f * (cw[2] - cw[0]);
                else if (j == 2) dt = 0.5f * (cw[3] - cw[1]);
                else             dt = (tc == 3) ? (cw[3] - cw[2]) : 0.5f * (wnext - cw[2]);

                float e = dt + cVv[1][j] * dxv + cVv[0][j] * dyv + cVv[2][j] * dzv
                        - Re * lap + dP[c][j] + fr[j];
                local += e * e;
                e4[j] += (c == 0) ? dyv : (c == 1) ? dxv : dzv;
            }
        }
#pragma unroll
        for (int j = 0; j < 4; j++) local += e4[j] * e4[j];

#pragma unroll
        for (int off = 16; off; off >>= 1)
            local += __shfl_down_sync(0xffffffffu, local, off);
        __shared__ float ws[24];
        if ((tid & 31) == 0) ws[tid >> 5] = local;
        __syncthreads();
        if (tid == 0) {
            float s = 0.f;
#pragma unroll
            for (int i = 0; i < 24; i++) s += ws[i];
            g_phy_part[bi] = (double)s;
        }
    }

    // ---------------- last-block final reduction ----------------
    __shared__ int isLast;
    if (tid == 0) {
        __threadfence();
        unsigned int t = atomicAdd(&g_counter, 1u);
        isLast = (t == FUSED_BLOCKS - 1) ? 1 : 0;
    }
    __syncthreads();
    if (isLast) {
        double s0 = 0.0, s1 = 0.0, s2 = 0.0, s3 = 0.0, s4 = 0.0;
        for (int i = tid; i < PHY_BLOCKS; i += 768) s0 += g_phy_part[i];
        for (int i = tid; i < MAIN_BLOCKS; i += 768) {
            s1 += g_mp[i * 4 + 0];
            s2 += g_mp[i * 4 + 1];
            s3 += g_mp[i * 4 + 2];
            s4 += g_mp[i * 4 + 3];
        }
#pragma unroll
        for (int off = 16; off; off >>= 1) {
            s0 += __shfl_down_sync(0xffffffffu, s0, off);
            s1 += __shfl_down_sync(0xffffffffu, s1, off);
            s2 += __shfl_down_sync(0xffffffffu, s2, off);
            s3 += __shfl_down_sync(0xffffffffu, s3, off);
            s4 += __shfl_down_sync(0xffffffffu, s4, off);
        }
        __shared__ double red[24][5];
        const int w = tid >> 5, l = tid & 31;
        if (l == 0) { red[w][0] = s0; red[w][1] = s1; red[w][2] = s2; red[w][3] = s3; red[w][4] = s4; }
        __syncthreads();
        if (tid == 0) {
            double a0 = 0, a1 = 0, a2 = 0, a3 = 0, a4 = 0;
#pragma unroll
            for (int i = 0; i < 24; i++) {
                a0 += red[i][0]; a1 += red[i][1]; a2 += red[i][2]; a3 += red[i][3]; a4 += red[i][4];
            }
            const double invN = 1.0 / (double)NTOT;
            double phy = a0 * invN;
            double m1  = a1 * invN;
            double m2  = a2 * invN;
            double t1  = a3 * invN;
            double t2  = a4 * invN;
            out[0] = (float)m1;
            out[1] = (float)m2;
            out[2] = (float)phy;
            out[3] = (float)((t1 < t2) ? (t2 - t1) : 0.0);
            __threadfence();
            g_counter = 0;   // reset for next graph replay
        }
    }
}

extern "C" void kernel_launch(void* const* d_in, const int* in_sizes, int n_in,
                              void* d_out, int out_size) {
    (void)in_sizes; (void)n_in; (void)out_size;
    const float* C  = (const float*)d_in[0];
    const float* V  = (const float*)d_in[1];
    const float* P  = (const float*)d_in[2];
    const float* X  = (const float*)d_in[3];
    const float* X1 = (const float*)d_in[4];
    const float* F  = (const float*)d_in[5];
    const float* Re = (const float*)d_in[6];
    const float* XL = (const float*)d_in[7];
    const float* Y  = (const float*)d_in[8];
    float* out = (float*)d_out;

    cudaFuncSetAttribute(k_fused, cudaFuncAttributeMaxDynamicSharedMemorySize, SMEM_BYTES);
    k_nop<<<1, 1>>>();   // keeps launch period = 2 so ncu (-s 5) lands on k_fused
    k_fused<<<FUSED_BLOCKS, 768, SMEM_BYTES>>>(V, P, F, Re, C, X, X1, Y, XL, out);
}

// round 4
// speedup vs baseline: 1.5052x; 1.3029x over previous
#include <cuda_runtime.h>

#define SS 48
#define TT 16
#define BB 2
#define NTOT (BB*SS*SS*SS*TT)   // 3,538,944

#define XT 4                    // x-tile per block
#define NXC (XT+4)              // 8 V columns in smem (halo 2)
#define PHY_BLOCKS (BB*SS*(SS/XT))      // 1152
#define SMEM_BYTES (NXC*48*48*4)        // 73728
#define COLBYTES (48*48*4)              // 9216 per column

__device__ double g_phy_part[PHY_BLOCKS];
__device__ double g_mp[PHY_BLOCKS * 4];
__device__ unsigned int g_counter = 0;

__device__ __forceinline__ unsigned int smem_u32(const void* p) {
    return (unsigned int)__cvta_generic_to_shared(p);
}

__device__ __forceinline__ void ld4g(const float* __restrict__ p, int off, float r[4]) {
    float4 v = __ldg(reinterpret_cast<const float4*>(p + off));
    r[0] = v.x; r[1] = v.y; r[2] = v.z; r[3] = v.w;
}
__device__ __forceinline__ void ld4s(const float* p, float r[4]) {
    float4 v = *reinterpret_cast<const float4*>(p);
    r[0] = v.x; r[1] = v.y; r[2] = v.z; r[3] = v.w;
}

// 3-tap coefficients for torch.gradient first derivative (with clamped reads)
__device__ __forceinline__ void coef1(int i, float a[3]) {
    bool lo = (i == 0), hi = (i == SS - 1);
    a[0] = lo ? 0.f  : (hi ? -1.f : -0.5f);
    a[1] = lo ? -1.f : (hi ?  1.f :  0.f );
    a[2] = lo ? 1.f  : (hi ?  0.f :  0.5f);
}
// 5-tap coefficients for grad(grad(f)) (exact composition, with clamped reads)
__device__ __forceinline__ void coef2(int i, float a[5]) {
    float c0 = 0.25f, c1 = 0.f, c2 = -0.5f, c3 = 0.f, c4 = 0.25f;
    if (i == 0)      { c0 = 0.f;   c1 = 0.f;   c2 = 0.5f;   c3 = -1.f;  c4 = 0.5f; }
    if (i == 1)      { c0 = 0.f;   c1 = 0.5f;  c2 = -0.75f; c3 = 0.f;   c4 = 0.25f; }
    if (i == SS - 2) { c0 = 0.25f; c1 = 0.f;   c2 = -0.75f; c3 = 0.5f;  c4 = 0.f; }
    if (i == SS - 1) { c0 = 0.5f;  c1 = -1.f;  c2 = 0.5f;   c3 = 0.f;   c4 = 0.f; }
    a[0] = c0; a[1] = c1; a[2] = c2; a[3] = c3; a[4] = c4;
}

__global__ void k_nop() {}

__global__ void __launch_bounds__(768, 1) k_fused(
    const float* __restrict__ V, const float* __restrict__ P,
    const float* __restrict__ F, const float* __restrict__ RePtr,
    const float* __restrict__ C, const float* __restrict__ X,
    const float* __restrict__ X1, const float* __restrict__ Y,
    const float* __restrict__ XL, float* __restrict__ out)
{
    extern __shared__ float sV[];   // [NXC][48z][48 floats]
    __shared__ __align__(8) unsigned long long mbar;
    __shared__ float ws[24];
    __shared__ float sm2[24][4];

    const int tid = threadIdx.x;
    const int bi  = blockIdx.x;
    const int xt  = bi % (SS / XT);
    const int y   = (bi / (SS / XT)) % SS;
    const int b   = bi / ((SS / XT) * SS);
    const int x0  = xt * XT;
    const int colbase = (b * SS + y) * SS;
    const unsigned int mb = smem_u32(&mbar);

    // ---- init mbarrier, then kick off bulk-async fill of the V tile ----
    if (tid == 0) {
        asm volatile("mbarrier.init.shared.b64 [%0], %1;" :: "r"(mb), "r"(1) : "memory");
    }
    __syncthreads();
    if (tid == 0) {
        asm volatile("mbarrier.arrive.expect_tx.shared.b64 _, [%0], %1;"
                     :: "r"(mb), "r"(SMEM_BYTES) : "memory");
#pragma unroll
        for (int col = 0; col < NXC; col++) {
            int gx = min(max(x0 - 2 + col, 0), SS - 1);
            const float* src = V + (size_t)(colbase + gx) * 2304;
            unsigned int dst = smem_u32(sV) + col * COLBYTES;
            asm volatile(
                "cp.async.bulk.shared::cta.global.mbarrier::complete_tx::bytes [%0], [%1], %2, [%3];"
                :: "r"(dst), "l"(src), "r"(COLBYTES), "r"(mb) : "memory");
        }
    }

    // ---- while the DMA runs: issue all independent gmem loads + coef math ----
    const int tc = tid & 3;
    const int z  = (tid >> 2) % 48;
    const int xk = (tid >> 2) / 48;
    const int x  = x0 + xk;
    const int xi = xk + 2;
    const int toff = tc * 4;
    const float Re = __ldg(RePtr);

    const int ym1 = max(y - 1, 0), ym2 = max(y - 2, 0);
    const int yp1 = min(y + 1, SS - 1), yp2 = min(y + 2, SS - 1);
    const int zm1 = max(z - 1, 0), zm2 = max(z - 2, 0);
    const int zp1 = min(z + 1, SS - 1), zp2 = min(z + 2, SS - 1);

    const int sc    = (colbase + x) * SS + z;
    const int s_ym1 = ((b * SS + ym1) * SS + x) * SS + z;
    const int s_ym2 = ((b * SS + ym2) * SS + x) * SS + z;
    const int s_yp1 = ((b * SS + yp1) * SS + x) * SS + z;
    const int s_yp2 = ((b * SS + yp2) * SS + x) * SS + z;

    // P rows (7 LDG.128) — independent of smem
    float pc[4], pzm[4], pzp[4], pxm[4], pxp[4], pym[4], pyp[4];
    ld4g(P, sc * 16 + toff, pc);
    ld4g(P, ((colbase + x) * SS + zm1) * 16 + toff, pzm);
    ld4g(P, ((colbase + x) * SS + zp1) * 16 + toff, pzp);
    ld4g(P, ((colbase + max(x - 1, 0)) * SS + z) * 16 + toff, pxm);
    ld4g(P, ((colbase + min(x + 1, SS - 1)) * SS + z) * 16 + toff, pxp);
    ld4g(P, s_ym1 * 16 + toff, pym);
    ld4g(P, s_yp1 * 16 + toff, pyp);

    // F rows (3 LDG.128) — independent of smem
    float fr0[4], fr1[4], fr2[4];
    ld4g(F, sc * 48 + 0  + toff, fr0);
    ld4g(F, sc * 48 + 16 + toff, fr1);
    ld4g(F, sc * 48 + 32 + toff, fr2);

    // stencil coefficients
    float zc1[3], zc2[5], yc1[3], yc2[5], xc1[3], xc2[5];
    coef1(z, zc1); coef2(z, zc2);
    coef1(y, yc1); coef2(y, yc2);
    coef1(x, xc1); coef2(x, xc2);

    // pressure gradient (frees P rows)
    float dP[3][4];
#pragma unroll
    for (int j = 0; j < 4; j++) {
        dP[0][j] = yc1[0] * pym[j] + yc1[1] * pc[j] + yc1[2] * pyp[j];
        dP[1][j] = xc1[0] * pxm[j] + xc1[1] * pc[j] + xc1[2] * pxp[j];
        dP[2][j] = zc1[0] * pzm[j] + zc1[1] * pc[j] + zc1[2] * pzp[j];
    }

    // ---- wait for the V tile ----
    {
        unsigned int done;
        do {
            asm volatile(
                "{\n\t.reg .pred p;\n\t"
                "mbarrier.try_wait.parity.shared.b64 p, [%1], %2, 0x989680;\n\t"
                "selp.b32 %0, 1, 0, p;\n\t}"
                : "=r"(done) : "r"(mb), "r"(0) : "memory");
        } while (!done);
    }

    // center velocities
    float cVv[3][4];
#pragma unroll
    for (int c = 0; c < 3; c++)
        ld4s(&sV[xi * 2304 + z * 48 + c * 16 + toff], cVv[c]);

    float e4[4] = {0.f, 0.f, 0.f, 0.f};
    float local = 0.f;

#pragma unroll
    for (int c = 0; c < 3; c++) {
        const int co = c * 16 + toff;
        float cw[4];
#pragma unroll
        for (int j = 0; j < 4; j++) cw[j] = cVv[c][j];

        float wprev = __shfl_up_sync(0xffffffffu, cw[3], 1);
        float wnext = __shfl_down_sync(0xffffffffu, cw[0], 1);

        float rym1[4], rym2[4], ryp1[4], ryp2[4];
        ld4g(V, s_ym1 * 48 + co, rym1);
        ld4g(V, s_ym2 * 48 + co, rym2);
        ld4g(V, s_yp1 * 48 + co, ryp1);
        ld4g(V, s_yp2 * 48 + co, ryp2);

        float rzm1[4], rzm2[4], rzp1[4], rzp2[4];
        ld4s(&sV[xi * 2304 + zm1 * 48 + co], rzm1);
        ld4s(&sV[xi * 2304 + zm2 * 48 + co], rzm2);
        ld4s(&sV[xi * 2304 + zp1 * 48 + co], rzp1);
        ld4s(&sV[xi * 2304 + zp2 * 48 + co], rzp2);

        float rxm1[4], rxm2[4], rxp1[4], rxp2[4];
        ld4s(&sV[(xi - 1) * 2304 + z * 48 + co], rxm1);
        ld4s(&sV[(xi - 2) * 2304 + z * 48 + co], rxm2);
        ld4s(&sV[(xi + 1) * 2304 + z * 48 + co], rxp1);
        ld4s(&sV[(xi + 2) * 2304 + z * 48 + co], rxp2);

        const float* fr = (c == 0) ? fr0 : (c == 1) ? fr1 : fr2;

#pragma unroll
        for (int j = 0; j < 4; j++) {
            float dyv = yc1[0] * rym1[j] + yc1[1] * cw[j] + yc1[2] * ryp1[j];
            float dxv = xc1[0] * rxm1[j] + xc1[1] * cw[j] + xc1[2] * rxp1[j];
            float dzv = zc1[0] * rzm1[j] + zc1[1] * cw[j] + zc1[2] * rzp1[j];

            float lap = yc2[0] * rym2[j] + yc2[1] * rym1[j] + yc2[2] * cw[j]
                      + yc2[3] * ryp1[j] + yc2[4] * ryp2[j];
            lap      += xc2[0] * rxm2[j] + xc2[1] * rxm1[j] + xc2[2] * cw[j]
                      + xc2[3] * rxp1[j] + xc2[4] * rxp2[j];
            lap      += zc2[0] * rzm2[j] + zc2[1] * rzm1[j] + zc2[2] * cw[j]
                      + zc2[3] * rzp1[j] + zc2[4] * rzp2[j];

            float dt;
            if (j == 0)      dt = (tc == 0) ? (cw[1] - cw[0]) : 0.5f * (cw[1] - wprev);
            else if (j == 1) dt = 0.5f * (cw[2] - cw[0]);
            else if (j == 2) dt = 0.5f * (cw[3] - cw[1]);
            else             dt = (tc == 3) ? (cw[3] - cw[2]) : 0.5f * (wnext - cw[2]);

            float e = dt + cVv[1][j] * dxv + cVv[0][j] * dyv + cVv[2][j] * dzv
                    - Re * lap + dP[c][j] + fr[j];
            local += e * e;
            e4[j] += (c == 0) ? dyv : (c == 1) ? dxv : dzv;
        }
    }
#pragma unroll
    for (int j = 0; j < 4; j++) local += e4[j] * e4[j];

#pragma unroll
    for (int off = 16; off; off >>= 1)
        local += __shfl_down_sync(0xffffffffu, local, off);
    if ((tid & 31) == 0) ws[tid >> 5] = local;

    // ---------------- streaming MSE slice for this block ----------------
    {
        const int g = bi * 768 + tid;   // chunk id (4 t-values)
        const int base = g * 4;
        float ca[4], xa[4], x1a[4], ya[4];
        ld4g(C, base, ca); ld4g(X, base, xa); ld4g(X1, base, x1a); ld4g(Y, base, ya);
        const int tcc = g & 3;
        float prev = (tcc == 0) ? __ldg(XL + (g >> 2)) : __ldg(Y + base - 1);
        float yl[4] = {prev, ya[0], ya[1], ya[2]};

        float m1 = 0.f, m2 = 0.f, t1 = 0.f, t2 = 0.f;
#pragma unroll
        for (int j = 0; j < 4; j++) {
            float a = x1a[j] - ya[j]; m1 += a * a;
            float bv = xa[j]  - ya[j]; m2 += bv * bv;
            float cv = ca[j]  - ya[j]; t2 += cv * cv;
            float dv = yl[j]  - ya[j]; t1 += dv * dv;
        }
#pragma unroll
        for (int off = 16; off; off >>= 1) {
            m1 += __shfl_down_sync(0xffffffffu, m1, off);
            m2 += __shfl_down_sync(0xffffffffu, m2, off);
            t1 += __shfl_down_sync(0xffffffffu, t1, off);
            t2 += __shfl_down_sync(0xffffffffu, t2, off);
        }
        const int w = tid >> 5, l = tid & 31;
        if (l == 0) { sm2[w][0] = m1; sm2[w][1] = m2; sm2[w][2] = t1; sm2[w][3] = t2; }
    }

    __syncthreads();
    if (tid == 0) {
        float s = 0.f;
        float a = 0.f, b2 = 0.f, c2 = 0.f, d2 = 0.f;
#pragma unroll
        for (int i = 0; i < 24; i++) {
            s += ws[i];
            a += sm2[i][0]; b2 += sm2[i][1]; c2 += sm2[i][2]; d2 += sm2[i][3];
        }
        g_phy_part[bi] = (double)s;
        g_mp[bi * 4 + 0] = (double)a;
        g_mp[bi * 4 + 1] = (double)b2;
        g_mp[bi * 4 + 2] = (double)c2;
        g_mp[bi * 4 + 3] = (double)d2;
    }

    // ---------------- last-block final reduction ----------------
    __shared__ int isLast;
    if (tid == 0) {
        __threadfence();
        unsigned int t = atomicAdd(&g_counter, 1u);
        isLast = (t == PHY_BLOCKS - 1) ? 1 : 0;
    }
    __syncthreads();
    if (isLast) {
        double s0 = 0.0, s1 = 0.0, s2 = 0.0, s3 = 0.0, s4 = 0.0;
        for (int i = tid; i < PHY_BLOCKS; i += 768) {
            s0 += g_phy_part[i];
            s1 += g_mp[i * 4 + 0];
            s2 += g_mp[i * 4 + 1];
            s3 += g_mp[i * 4 + 2];
            s4 += g_mp[i * 4 + 3];
        }
#pragma unroll
        for (int off = 16; off; off >>= 1) {
            s0 += __shfl_down_sync(0xffffffffu, s0, off);
            s1 += __shfl_down_sync(0xffffffffu, s1, off);
            s2 += __shfl_down_sync(0xffffffffu, s2, off);
            s3 += __shfl_down_sync(0xffffffffu, s3, off);
            s4 += __shfl_down_sync(0xffffffffu, s4, off);
        }
        __shared__ double red[24][5];
        const int w = tid >> 5, l = tid & 31;
        if (l == 0) { red[w][0] = s0; red[w][1] = s1; red[w][2] = s2; red[w][3] = s3; red[w][4] = s4; }
        __syncthreads();
        if (tid == 0) {
            double a0 = 0, a1 = 0, a2 = 0, a3 = 0, a4 = 0;
#pragma unroll
            for (int i = 0; i < 24; i++) {
                a0 += red[i][0]; a1 += red[i][1]; a2 += red[i][2]; a3 += red[i][3]; a4 += red[i][4];
            }
            const double invN = 1.0 / (double)NTOT;
            double phy = a0 * invN;
            double m1  = a1 * invN;
            double m2  = a2 * invN;
            double t1  = a3 * invN;
            double t2  = a4 * invN;
            out[0] = (float)m1;
            out[1] = (float)m2;
            out[2] = (float)phy;
            out[3] = (float)((t1 < t2) ? (t2 - t1) : 0.0);
            __threadfence();
            g_counter = 0;   // reset for next graph replay
        }
    }
}

extern "C" void kernel_launch(void* const* d_in, const int* in_sizes, int n_in,
                              void* d_out, int out_size) {
    (void)in_sizes; (void)n_in; (void)out_size;
    const float* C  = (const float*)d_in[0];
    const float* V  = (const float*)d_in[1];
    const float* P  = (const float*)d_in[2];
    const float* X  = (const float*)d_in[3];
    const float* X1 = (const float*)d_in[4];
    const float* F  = (const float*)d_in[5];
    const float* Re = (const float*)d_in[6];
    const float* XL = (const float*)d_in[7];
    const float* Y  = (const float*)d_in[8];
    float* out = (float*)d_out;

    cudaFuncSetAttribute(k_fused, cudaFuncAttributeMaxDynamicSharedMemorySize, SMEM_BYTES);
    k_nop<<<1, 1>>>();   // keeps launch period = 2 so ncu (-s 5) lands on k_fused
    k_fused<<<PHY_BLOCKS, 768, SMEM_BYTES>>>(V, P, F, Re, C, X, X1, Y, XL, out);
}